// round 1
// baseline (speedup 1.0000x reference)
#include <cuda_runtime.h>

#define BB 2
#define CC 128
#define NN 10000
#define KK 16
#define TILE_N 64

// Scratch (static device allocations are allowed)
__device__ __align__(16) float g_wh[BB * NN * CC];   // node-major: [b][n][c]
__device__ float g_s1[BB * NN];
__device__ float g_s2[BB * NN];
__device__ float g_Wt[CC * CC];                      // W transposed: [c][o]
__device__ float g_aW1[CC];
__device__ float g_aW2[CC];

// ---------------------------------------------------------------------------
// Kernel 0: transpose W and fold attention vector into W:
//   aW1[c] = sum_o a[o]   * W[o][c]
//   aW2[c] = sum_o a[C+o] * W[o][c]
// ---------------------------------------------------------------------------
__global__ void prep_kernel(const float* __restrict__ W, const float* __restrict__ a) {
    int tid = threadIdx.x;  // 256 threads
    for (int i = tid; i < CC * CC; i += 256) {
        int o = i >> 7;
        int c = i & 127;
        g_Wt[c * CC + o] = W[i];
    }
    if (tid < CC) {
        float s1 = 0.f, s2 = 0.f;
        for (int o = 0; o < CC; o++) {
            float w = W[o * CC + tid];
            s1 += a[o] * w;
            s2 += a[CC + o] * w;
        }
        g_aW1[tid] = s1;
        g_aW2[tid] = s2;
    }
}

// ---------------------------------------------------------------------------
// Kernel 1: wh[b][n][o] = sum_c W[o][c] * x[b][c][n]   (node-major output)
// plus s1[b][n] = aW1 . x[b][:][n],  s2[b][n] = aW2 . x[b][:][n]
// 256 threads; thread computes output channel o = tid&127 for 2 groups of
// 16 nodes (group-half = tid>>7). x tile staged in smem (broadcast reads).
// ---------------------------------------------------------------------------
__global__ void gemm_kernel(const float* __restrict__ x) {
    __shared__ __align__(16) float x_s[CC][TILE_N];  // 32 KB

    int b = blockIdx.y;
    int n0 = blockIdx.x * TILE_N;
    int tid = threadIdx.x;

    // Load x tile [c][nn], coalesced along n; zero-pad past N.
    for (int idx = tid; idx < CC * TILE_N; idx += 256) {
        int c = idx >> 6;           // /64
        int nn = idx & 63;
        int n = n0 + nn;
        x_s[c][nn] = (n < NN) ? x[((size_t)b * CC + c) * NN + n] : 0.f;
    }
    __syncthreads();

    int o = tid & 127;
    int gh = tid >> 7;  // 0 or 1
    const float4* xs4 = (const float4*)&x_s[0][0];  // [c][16] float4 view

    for (int g2 = 0; g2 < 2; g2++) {
        int g = gh * 2 + g2;  // node group 0..3 (16 nodes each)
        float acc[16];
#pragma unroll
        for (int m = 0; m < 16; m++) acc[m] = 0.f;

#pragma unroll 4
        for (int c = 0; c < CC; c++) {
            float w = g_Wt[c * CC + o];  // coalesced, L1-resident
            float4 v0 = xs4[c * 16 + g * 4 + 0];  // smem broadcast
            float4 v1 = xs4[c * 16 + g * 4 + 1];
            float4 v2 = xs4[c * 16 + g * 4 + 2];
            float4 v3 = xs4[c * 16 + g * 4 + 3];
            acc[0]  += w * v0.x;  acc[1]  += w * v0.y;
            acc[2]  += w * v0.z;  acc[3]  += w * v0.w;
            acc[4]  += w * v1.x;  acc[5]  += w * v1.y;
            acc[6]  += w * v1.z;  acc[7]  += w * v1.w;
            acc[8]  += w * v2.x;  acc[9]  += w * v2.y;
            acc[10] += w * v2.z;  acc[11] += w * v2.w;
            acc[12] += w * v3.x;  acc[13] += w * v3.y;
            acc[14] += w * v3.z;  acc[15] += w * v3.w;
        }

        int nbase = n0 + g * 16;
#pragma unroll
        for (int m = 0; m < 16; m++) {
            int n = nbase + m;
            if (n < NN) g_wh[((size_t)b * NN + n) * CC + o] = acc[m];
        }
    }

    // s1 / s2: 128 tasks (64 nodes x {s1,s2}) on threads 0..127
    if (tid < 2 * TILE_N) {
        int which = tid >> 6;        // 0 -> s1, 1 -> s2
        int nn = tid & 63;
        int n = n0 + nn;
        if (n < NN) {
            const float* aw = which ? g_aW2 : g_aW1;
            float s = 0.f;
#pragma unroll 8
            for (int c = 0; c < CC; c++) s += aw[c] * x_s[c][nn];
            if (which) g_s2[b * NN + n] = s;
            else       g_s1[b * NN + n] = s;
        }
    }
}

// ---------------------------------------------------------------------------
// Kernel 2: attention + aggregation. One warp per node (16 nodes / block).
//   e_k = lrelu(s1[i_k] + s2[j_k]); A = softmax_k(e)
//   h[c] = sum_k A_k * wh[b][j_k][c]     (coalesced 512B gathers)
// Output transposed back to [b][c][n] via smem staging (stride-132 pad).
// ---------------------------------------------------------------------------
__global__ void gat_kernel(const int* __restrict__ ei, float* __restrict__ out) {
    __shared__ float hs[16 * 132];  // [node_local][c], padded

    int tid = threadIdx.x;  // 512
    int lane = tid & 31;
    int w = tid >> 5;       // node within block, 0..15
    int b = blockIdx.y;
    int n0 = blockIdx.x * 16;
    int n = n0 + w;

    // both half-warps compute identical k = lane&15 (keeps reductions simple)
    int kk = lane & 15;
    int j = ei[(((size_t)0 * BB + b) * NN + n) * KK + kk];  // edge_index[0] -> j
    int i = ei[(((size_t)1 * BB + b) * NN + n) * KK + kk];  // edge_index[1] -> i

    float e = g_s1[b * NN + i] + g_s2[b * NN + j];
    e = (e > 0.f) ? e : 0.2f * e;  // leaky relu

    // softmax over the 16-lane group (xor masks < 16 stay in-group)
    float em = e;
#pragma unroll
    for (int m = 8; m; m >>= 1) em = fmaxf(em, __shfl_xor_sync(0xffffffffu, em, m));
    float p = __expf(e - em);
    float ps = p;
#pragma unroll
    for (int m = 8; m; m >>= 1) ps += __shfl_xor_sync(0xffffffffu, ps, m);
    float A = p / ps;

    // weighted gather-accumulate: each lane owns 4 channels (float4)
    const float4* whb = ((const float4*)g_wh) + (size_t)b * NN * (CC / 4);
    float4 acc = make_float4(0.f, 0.f, 0.f, 0.f);
#pragma unroll
    for (int k = 0; k < 16; k++) {
        float Ak = __shfl_sync(0xffffffffu, A, k);
        int jk   = __shfl_sync(0xffffffffu, j, k);
        float4 v = whb[(size_t)jk * (CC / 4) + lane];
        acc.x += Ak * v.x;
        acc.y += Ak * v.y;
        acc.z += Ak * v.z;
        acc.w += Ak * v.w;
    }

    // stage [node][c] in smem (row stride 132 floats: 16B-aligned, low conflicts)
    *(float4*)&hs[w * 132 + lane * 4] = acc;
    __syncthreads();

    // coalesced transposed write: out[b][c][n0+nl]
#pragma unroll
    for (int r = 0; r < 4; r++) {
        int c = (tid >> 4) + r * 32;
        int nl = tid & 15;
        out[((size_t)b * CC + c) * NN + n0 + nl] = hs[nl * 132 + c];
    }
}

// ---------------------------------------------------------------------------
extern "C" void kernel_launch(void* const* d_in, const int* in_sizes, int n_in,
                              void* d_out, int out_size) {
    const float* x = (const float*)d_in[0];       // [B,C,N,1]
    const int* ei  = (const int*)d_in[1];         // [2,B,N,K]
    const float* W = (const float*)d_in[2];       // [C,C]
    const float* a = (const float*)d_in[3];       // [2C]
    float* out     = (float*)d_out;               // [B,C,N,1]

    prep_kernel<<<1, 256>>>(W, a);
    gemm_kernel<<<dim3((NN + TILE_N - 1) / TILE_N, BB), 256>>>(x);
    gat_kernel<<<dim3(NN / 16, BB), 512>>>(ei, out);
}

// round 2
// speedup vs baseline: 1.2640x; 1.2640x over previous
#include <cuda_runtime.h>

#define BB 2
#define CC 128
#define NN 10000
#define KK 16

// Scratch (static device arrays are allowed)
__device__ __align__(16) float g_wh[BB * NN * CC];   // node-major: [b][n][c]
__device__ float g_s1[BB * NN];
__device__ float g_s2[BB * NN];
__device__ __align__(16) float g_Wt[CC * CC];        // W transposed: [c][o]
__device__ float g_aW1[CC];
__device__ float g_aW2[CC];

// ---------------------------------------------------------------------------
// Kernel 0 (parallel): transpose W into g_Wt and fold attention vector:
//   aW1[c] = sum_o a[o]   * W[o][c],  aW2[c] = sum_o a[C+o] * W[o][c]
// 32 blocks x 256 threads: one warp per (which, c) dot product.
// ---------------------------------------------------------------------------
__global__ void prep_kernel(const float* __restrict__ W, const float* __restrict__ a) {
    int t = blockIdx.x * 256 + threadIdx.x;   // 8192 threads

    // Transpose (2 elements per thread)
    for (int i = t; i < CC * CC; i += 8192) {
        int o = i >> 7;
        int c = i & 127;
        g_Wt[c * CC + o] = W[i];
    }

    // 256 dot products of length 128, one warp each
    int wg = t >> 5;       // 0..255
    int lane = t & 31;
    int which = wg >> 7;   // 0 -> aW1, 1 -> aW2
    int c = wg & 127;
    float s = 0.f;
#pragma unroll
    for (int r = 0; r < 4; r++) {
        int o = lane + r * 32;
        s += a[which * CC + o] * W[o * CC + c];
    }
#pragma unroll
    for (int m = 16; m; m >>= 1) s += __shfl_xor_sync(0xffffffffu, s, m);
    if (lane == 0) {
        if (which) g_aW2[c] = s;
        else       g_aW1[c] = s;
    }
}

// ---------------------------------------------------------------------------
// Kernel 1: register-tiled GEMM. Block tile = 128 o x 128 n, full K=128 in
// four 32-c chunks (x & Wt staged in smem). Thread micro-tile = 8o x 8n
// (64 FMA per 64 B of LDS -> FMA-bound, not smem-bound).
// Also computes s1/s2 from the same x tiles.
// Output wh is node-major [b][n][o] for the gather kernel.
// ---------------------------------------------------------------------------
__global__ void __launch_bounds__(256) gemm_kernel(const float* __restrict__ x) {
    __shared__ __align__(16) float x_s[32][128];   // 16 KB
    __shared__ __align__(16) float w_s[32][128];   // 16 KB  (w_s[c][o])
    __shared__ float aw_s[2][32];

    int b = blockIdx.y;
    int n0 = blockIdx.x * 128;
    int tid = threadIdx.x;

    int n_grp = tid & 15;          // 16 groups of 8 nodes
    int o_grp = tid >> 4;          // 16 groups of 8 channels
    int nb = n_grp * 8;
    int ob = o_grp * 8;

    int s_which = tid >> 7;        // s1 or s2 task
    int s_n = tid & 127;

    float acc[8][8];
#pragma unroll
    for (int i = 0; i < 8; i++)
#pragma unroll
        for (int j = 0; j < 8; j++) acc[i][j] = 0.f;
    float s_acc = 0.f;

    for (int c0 = 0; c0 < CC; c0 += 32) {
        // Stage chunk: x coalesced along n, Wt coalesced along o
#pragma unroll
        for (int it = 0; it < 16; it++) {
            int idx = it * 256 + tid;
            int c = idx >> 7;
            int nn = idx & 127;
            int n = n0 + nn;
            x_s[c][nn] = (n < NN) ? x[((size_t)b * CC + c0 + c) * NN + n] : 0.f;
            w_s[c][nn] = g_Wt[(c0 + c) * CC + nn];
        }
        if (tid < 64) {
            int wch = tid >> 5, cc = tid & 31;
            aw_s[wch][cc] = wch ? g_aW2[c0 + cc] : g_aW1[c0 + cc];
        }
        __syncthreads();

#pragma unroll 4
        for (int cc = 0; cc < 32; cc++) {
            float4 xv0 = *(const float4*)&x_s[cc][nb];
            float4 xv1 = *(const float4*)&x_s[cc][nb + 4];
            float4 wv0 = *(const float4*)&w_s[cc][ob];
            float4 wv1 = *(const float4*)&w_s[cc][ob + 4];
            float xr[8] = {xv0.x, xv0.y, xv0.z, xv0.w, xv1.x, xv1.y, xv1.z, xv1.w};
            float wr[8] = {wv0.x, wv0.y, wv0.z, wv0.w, wv1.x, wv1.y, wv1.z, wv1.w};
#pragma unroll
            for (int i = 0; i < 8; i++)
#pragma unroll
                for (int j = 0; j < 8; j++)
                    acc[i][j] += wr[i] * xr[j];
        }

        // s1/s2 partial sums (lanes read consecutive n -> conflict-free)
#pragma unroll 8
        for (int cc = 0; cc < 32; cc++)
            s_acc += aw_s[s_which][cc] * x_s[cc][s_n];

        __syncthreads();
    }

    // Store wh node-major (2 float4 per node row)
#pragma unroll
    for (int j = 0; j < 8; j++) {
        int n = n0 + nb + j;
        if (n < NN) {
            float* dst = &g_wh[((size_t)b * NN + n) * CC + ob];
            *(float4*)(dst)     = make_float4(acc[0][j], acc[1][j], acc[2][j], acc[3][j]);
            *(float4*)(dst + 4) = make_float4(acc[4][j], acc[5][j], acc[6][j], acc[7][j]);
        }
    }

    if (n0 + s_n < NN) {
        if (s_which) g_s2[b * NN + n0 + s_n] = s_acc;
        else         g_s1[b * NN + n0 + s_n] = s_acc;
    }
}

// ---------------------------------------------------------------------------
// Kernel 2: attention + aggregation. One warp per node (16 nodes / block).
//   e_k = lrelu(s1[i_k] + s2[j_k]); A = softmax_k(e)
//   h[c] = sum_k A_k * wh[b][j_k][c]     (coalesced 512B gathers)
// Output transposed back to [b][c][n] via smem staging.
// ---------------------------------------------------------------------------
__global__ void __launch_bounds__(512) gat_kernel(const int* __restrict__ ei,
                                                  float* __restrict__ out) {
    __shared__ float hs[16 * 132];  // [node_local][c], padded stride

    int tid = threadIdx.x;  // 512
    int lane = tid & 31;
    int w = tid >> 5;       // node within block, 0..15
    int b = blockIdx.y;
    int n0 = blockIdx.x * 16;
    int n = n0 + w;

    int kk = lane & 15;
    int j = ei[(((size_t)0 * BB + b) * NN + n) * KK + kk];  // edge_index[0] -> j
    int i = ei[(((size_t)1 * BB + b) * NN + n) * KK + kk];  // edge_index[1] -> i

    float e = g_s1[b * NN + i] + g_s2[b * NN + j];
    e = (e > 0.f) ? e : 0.2f * e;  // leaky relu

    float em = e;
#pragma unroll
    for (int m = 8; m; m >>= 1) em = fmaxf(em, __shfl_xor_sync(0xffffffffu, em, m));
    float p = __expf(e - em);
    float ps = p;
#pragma unroll
    for (int m = 8; m; m >>= 1) ps += __shfl_xor_sync(0xffffffffu, ps, m);
    float A = p / ps;

    const float4* whb = ((const float4*)g_wh) + (size_t)b * NN * (CC / 4);
    float4 acc = make_float4(0.f, 0.f, 0.f, 0.f);
#pragma unroll
    for (int k = 0; k < 16; k++) {
        float Ak = __shfl_sync(0xffffffffu, A, k);
        int jk   = __shfl_sync(0xffffffffu, j, k);
        float4 v = whb[(size_t)jk * (CC / 4) + lane];
        acc.x += Ak * v.x;
        acc.y += Ak * v.y;
        acc.z += Ak * v.z;
        acc.w += Ak * v.w;
    }

    *(float4*)&hs[w * 132 + lane * 4] = acc;
    __syncthreads();

#pragma unroll
    for (int r = 0; r < 4; r++) {
        int c = (tid >> 4) + r * 32;
        int nl = tid & 15;
        out[((size_t)b * CC + c) * NN + n0 + nl] = hs[nl * 132 + c];
    }
}

// ---------------------------------------------------------------------------
extern "C" void kernel_launch(void* const* d_in, const int* in_sizes, int n_in,
                              void* d_out, int out_size) {
    const float* x = (const float*)d_in[0];       // [B,C,N,1]
    const int* ei  = (const int*)d_in[1];         // [2,B,N,K]
    const float* W = (const float*)d_in[2];       // [C,C]
    const float* a = (const float*)d_in[3];       // [2C]
    float* out     = (float*)d_out;               // [B,C,N,1]

    prep_kernel<<<32, 256>>>(W, a);
    gemm_kernel<<<dim3((NN + 127) / 128, BB), 256>>>(x);
    gat_kernel<<<dim3(NN / 16, BB), 512>>>(ei, out);
}

// round 3
// speedup vs baseline: 1.7413x; 1.3776x over previous
#include <cuda_runtime.h>
#include <cuda_fp16.h>

#define BB 2
#define CC 128
#define NN 10000
#define KK 16
#define TN 68          // nodes per gemm block: 148 blocks exactly
#define NTHR 272       // 16 o-groups x 17 n-groups

// Scratch (static device arrays are allowed)
__device__ __align__(16) __half g_whh[BB * NN * CC];  // node-major: [b][n][c], fp16
__device__ float g_s1[BB * NN];
__device__ float g_s2[BB * NN];

// ---------------------------------------------------------------------------
// Kernel 1: fused GEMM. Block tile = 128 o x 68 n, K=128 in four 32-c chunks.
// W transposed in smem per block (no prep kernel). s1/s2 derived from the wh
// accumulators: s1[n] = sum_o a[o]*wh[o][n]. Grid = (148, B): exactly 2 equal
// blocks per SM -> balanced FMA makespan.
// ---------------------------------------------------------------------------
__global__ void __launch_bounds__(NTHR) gemm_kernel(const float* __restrict__ x,
                                                    const float* __restrict__ W,
                                                    const float* __restrict__ a) {
    __shared__ __align__(16) float w_s[32][132];      // [c][o], padded
    __shared__ __align__(16) float x_s[32][TN];       // [c][n]
    __shared__ float s_red[2][16][TN];
    __shared__ float a_s[2 * CC];

    int b = blockIdx.y;
    int n0 = blockIdx.x * TN;
    int tid = threadIdx.x;

    int n_grp = tid % 17;   // 17 groups of 4 nodes
    int o_grp = tid / 17;   // 16 groups of 8 channels
    int nb = n_grp * 4;
    int ob = o_grp * 8;

    if (tid < 2 * CC) a_s[tid] = a[tid];

    float acc[8][4];
#pragma unroll
    for (int i = 0; i < 8; i++)
#pragma unroll
        for (int j = 0; j < 4; j++) acc[i][j] = 0.f;

    for (int c0 = 0; c0 < CC; c0 += 32) {
        // Stage W chunk transposed: read coalesced along c, store [c][o]
        for (int idx = tid; idx < 32 * 128; idx += NTHR) {
            int c = idx & 31;
            int o = idx >> 5;
            w_s[c][o] = W[o * CC + c0 + c];
        }
        // Stage x chunk: coalesced along n
        for (int idx = tid; idx < 32 * TN; idx += NTHR) {
            int c = idx / TN;
            int nn = idx % TN;
            int n = n0 + nn;
            x_s[c][nn] = (n < NN) ? x[((size_t)(b * CC + c0 + c)) * NN + n] : 0.f;
        }
        __syncthreads();

#pragma unroll 8
        for (int cc = 0; cc < 32; cc++) {
            float4 xv  = *(const float4*)&x_s[cc][nb];
            float4 wv0 = *(const float4*)&w_s[cc][ob];
            float4 wv1 = *(const float4*)&w_s[cc][ob + 4];
            float wr[8] = {wv0.x, wv0.y, wv0.z, wv0.w, wv1.x, wv1.y, wv1.z, wv1.w};
            float xr[4] = {xv.x, xv.y, xv.z, xv.w};
#pragma unroll
            for (int i = 0; i < 8; i++)
#pragma unroll
                for (int j = 0; j < 4; j++)
                    acc[i][j] += wr[i] * xr[j];
        }
        __syncthreads();
    }

    // s1/s2 partials from accumulators
    {
        float sp1[4] = {0.f, 0.f, 0.f, 0.f};
        float sp2[4] = {0.f, 0.f, 0.f, 0.f};
#pragma unroll
        for (int i = 0; i < 8; i++) {
            float a1 = a_s[ob + i];
            float a2 = a_s[CC + ob + i];
#pragma unroll
            for (int j = 0; j < 4; j++) {
                sp1[j] += a1 * acc[i][j];
                sp2[j] += a2 * acc[i][j];
            }
        }
#pragma unroll
        for (int j = 0; j < 4; j++) {
            s_red[0][o_grp][nb + j] = sp1[j];
            s_red[1][o_grp][nb + j] = sp2[j];
        }
    }

    // Store wh as fp16, node-major
#pragma unroll
    for (int j = 0; j < 4; j++) {
        int n = n0 + nb + j;
        if (n < NN) {
            __half2 p[4];
            p[0] = __floats2half2_rn(acc[0][j], acc[1][j]);
            p[1] = __floats2half2_rn(acc[2][j], acc[3][j]);
            p[2] = __floats2half2_rn(acc[4][j], acc[5][j]);
            p[3] = __floats2half2_rn(acc[6][j], acc[7][j]);
            *(uint4*)&g_whh[((size_t)b * NN + n) * CC + ob] = *(uint4*)p;
        }
    }

    __syncthreads();

    // Reduce s partials over 16 o-groups
    if (tid < 2 * TN) {
        int which = tid >= TN;
        int nn = which ? tid - TN : tid;
        float s = 0.f;
#pragma unroll
        for (int og = 0; og < 16; og++) s += s_red[which][og][nn];
        int n = n0 + nn;
        if (n < NN) {
            if (which) g_s2[b * NN + n] = s;
            else       g_s1[b * NN + n] = s;
        }
    }
}

// ---------------------------------------------------------------------------
// Kernel 2: attention + aggregation. One warp per node (16 nodes / block).
//   e_k = lrelu(s1[i_k] + s2[j_k]); A = softmax_k(e)
//   h[c] = sum_k A_k * wh_h[b][j_k][c]   (coalesced 256B fp16 gathers)
// Output transposed to [b][c][n] via smem staging.
// ---------------------------------------------------------------------------
__global__ void __launch_bounds__(512) gat_kernel(const int* __restrict__ ei,
                                                  float* __restrict__ out) {
    __shared__ float hs[16 * 132];  // [node_local][c], padded stride

    int tid = threadIdx.x;  // 512
    int lane = tid & 31;
    int w = tid >> 5;       // node within block, 0..15
    int b = blockIdx.y;
    int n0 = blockIdx.x * 16;
    int n = n0 + w;

    int kk = lane & 15;
    int j = ei[(((size_t)0 * BB + b) * NN + n) * KK + kk];  // edge_index[0] -> j
    int i = ei[(((size_t)1 * BB + b) * NN + n) * KK + kk];  // edge_index[1] -> i

    float e = g_s1[b * NN + i] + g_s2[b * NN + j];
    e = (e > 0.f) ? e : 0.2f * e;  // leaky relu

    float em = e;
#pragma unroll
    for (int m = 8; m; m >>= 1) em = fmaxf(em, __shfl_xor_sync(0xffffffffu, em, m));
    float p = __expf(e - em);
    float ps = p;
#pragma unroll
    for (int m = 8; m; m >>= 1) ps += __shfl_xor_sync(0xffffffffu, ps, m);
    float A = p / ps;

    // fp16 gather: row = 256 B = 32 uint2; lane owns channels [lane*4, lane*4+4)
    const uint2* whb = (const uint2*)g_whh + (size_t)b * NN * 32;
    float4 acc = make_float4(0.f, 0.f, 0.f, 0.f);
#pragma unroll
    for (int k = 0; k < 16; k++) {
        float Ak = __shfl_sync(0xffffffffu, A, k);
        int jk   = __shfl_sync(0xffffffffu, j, k);
        uint2 v = whb[(size_t)jk * 32 + lane];
        __half2 h0 = *reinterpret_cast<__half2*>(&v.x);
        __half2 h1 = *reinterpret_cast<__half2*>(&v.y);
        float2 f0 = __half22float2(h0);
        float2 f1 = __half22float2(h1);
        acc.x += Ak * f0.x;
        acc.y += Ak * f0.y;
        acc.z += Ak * f1.x;
        acc.w += Ak * f1.y;
    }

    *(float4*)&hs[w * 132 + lane * 4] = acc;
    __syncthreads();

#pragma unroll
    for (int r = 0; r < 4; r++) {
        int c = (tid >> 4) + r * 32;
        int nl = tid & 15;
        out[((size_t)b * CC + c) * NN + n0 + nl] = hs[nl * 132 + c];
    }
}

// ---------------------------------------------------------------------------
extern "C" void kernel_launch(void* const* d_in, const int* in_sizes, int n_in,
                              void* d_out, int out_size) {
    const float* x = (const float*)d_in[0];       // [B,C,N,1]
    const int* ei  = (const int*)d_in[1];         // [2,B,N,K]
    const float* W = (const float*)d_in[2];       // [C,C]
    const float* a = (const float*)d_in[3];       // [2C]
    float* out     = (float*)d_out;               // [B,C,N,1]

    gemm_kernel<<<dim3(148, BB), NTHR>>>(x, W, a);
    gat_kernel<<<dim3(NN / 16, BB), 512>>>(ei, out);
}

// round 4
// speedup vs baseline: 1.7562x; 1.0086x over previous
#include <cuda_runtime.h>
#include <cuda_fp16.h>

#define BB 2
#define CC 128
#define NN 10000
#define KK 16
#define TN 68          // nodes per gemm block: grid (148, B), 2 equal blocks/SM
#define NTHR 272       // 16 o-groups x 17 n-groups

// Scratch (static device arrays are allowed)
__device__ __align__(16) __half g_whh[BB * NN * CC];  // node-major: [b][n][c], fp16
__device__ float g_s1[BB * NN];
__device__ float g_s2[BB * NN];

// Packed fp32x2 FMA (sm_100+): d = a * b + d, elementwise on 2 floats.
__device__ __forceinline__ void ffma2(unsigned long long& d,
                                      unsigned long long a,
                                      unsigned long long b) {
    asm("fma.rn.f32x2 %0, %1, %2, %0;" : "+l"(d) : "l"(a), "l"(b));
}
__device__ __forceinline__ unsigned long long bcast2(float v) {
    unsigned long long r;
    asm("mov.b64 %0, {%1, %1};" : "=l"(r) : "f"(v));
    return r;
}

// ---------------------------------------------------------------------------
// Kernel 1: fused GEMM with packed f32x2 FMAs. Block tile = 128 o x 68 n,
// K=128 in four 32-c chunks. Accumulators pair adjacent o-channels so the
// w-operand f32x2 pairs fall directly out of the LDS.128 of w_s.
// s1/s2 derived from the accumulators. wh stored fp16 node-major.
// ---------------------------------------------------------------------------
__global__ void __launch_bounds__(NTHR) gemm_kernel(const float* __restrict__ x,
                                                    const float* __restrict__ W,
                                                    const float* __restrict__ a) {
    __shared__ __align__(16) float w_s[32][132];      // [c][o], padded (528B rows)
    __shared__ __align__(16) float x_s[32][TN];       // [c][n]  (272B rows)
    __shared__ float s_red[2][16][TN];
    __shared__ float a_s[2 * CC];

    int b = blockIdx.y;
    int n0 = blockIdx.x * TN;
    int tid = threadIdx.x;

    int n_grp = tid % 17;   // 17 groups of 4 nodes
    int o_grp = tid / 17;   // 16 groups of 8 channels
    int nb = n_grp * 4;
    int ob = o_grp * 8;

    if (tid < 2 * CC) a_s[tid] = a[tid];

    // acc2[i2][j]: f32x2 pair of channels (ob+2*i2, ob+2*i2+1) for node nb+j
    unsigned long long acc2[4][4];
    unsigned long long zz = bcast2(0.f);
#pragma unroll
    for (int i = 0; i < 4; i++)
#pragma unroll
        for (int j = 0; j < 4; j++) acc2[i][j] = zz;

    for (int c0 = 0; c0 < CC; c0 += 32) {
        // Stage W chunk transposed: read coalesced along c, store [c][o]
        for (int idx = tid; idx < 32 * 128; idx += NTHR) {
            int c = idx & 31;
            int o = idx >> 5;
            w_s[c][o] = W[o * CC + c0 + c];
        }
        // Stage x chunk: coalesced along n
        for (int idx = tid; idx < 32 * TN; idx += NTHR) {
            int c = idx / TN;
            int nn = idx % TN;
            int n = n0 + nn;
            x_s[c][nn] = (n < NN) ? x[((size_t)(b * CC + c0 + c)) * NN + n] : 0.f;
        }
        __syncthreads();

#pragma unroll 8
        for (int cc = 0; cc < 32; cc++) {
            float4 xv = *(const float4*)&x_s[cc][nb];
            // Two LDS.128 of w give four (w,w+1) f32x2 pairs for free
            ulonglong2 wa = *(const ulonglong2*)&w_s[cc][ob];
            ulonglong2 wb = *(const ulonglong2*)&w_s[cc][ob + 4];
            unsigned long long xb[4];
            xb[0] = bcast2(xv.x);
            xb[1] = bcast2(xv.y);
            xb[2] = bcast2(xv.z);
            xb[3] = bcast2(xv.w);
#pragma unroll
            for (int j = 0; j < 4; j++) {
                ffma2(acc2[0][j], wa.x, xb[j]);
                ffma2(acc2[1][j], wa.y, xb[j]);
                ffma2(acc2[2][j], wb.x, xb[j]);
                ffma2(acc2[3][j], wb.y, xb[j]);
            }
        }
        __syncthreads();
    }

    // Unpack accumulators to scalars
    float accf[8][4];
#pragma unroll
    for (int i2 = 0; i2 < 4; i2++)
#pragma unroll
        for (int j = 0; j < 4; j++) {
            float lo, hi;
            asm("mov.b64 {%0, %1}, %2;" : "=f"(lo), "=f"(hi) : "l"(acc2[i2][j]));
            accf[2 * i2][j] = lo;
            accf[2 * i2 + 1][j] = hi;
        }

    // s1/s2 partials from accumulators
    {
        float sp1[4] = {0.f, 0.f, 0.f, 0.f};
        float sp2[4] = {0.f, 0.f, 0.f, 0.f};
#pragma unroll
        for (int i = 0; i < 8; i++) {
            float a1 = a_s[ob + i];
            float a2 = a_s[CC + ob + i];
#pragma unroll
            for (int j = 0; j < 4; j++) {
                sp1[j] += a1 * accf[i][j];
                sp2[j] += a2 * accf[i][j];
            }
        }
#pragma unroll
        for (int j = 0; j < 4; j++) {
            s_red[0][o_grp][nb + j] = sp1[j];
            s_red[1][o_grp][nb + j] = sp2[j];
        }
    }

    // Store wh as fp16, node-major
#pragma unroll
    for (int j = 0; j < 4; j++) {
        int n = n0 + nb + j;
        if (n < NN) {
            __half2 p[4];
            p[0] = __floats2half2_rn(accf[0][j], accf[1][j]);
            p[1] = __floats2half2_rn(accf[2][j], accf[3][j]);
            p[2] = __floats2half2_rn(accf[4][j], accf[5][j]);
            p[3] = __floats2half2_rn(accf[6][j], accf[7][j]);
            *(uint4*)&g_whh[((size_t)b * NN + n) * CC + ob] = *(uint4*)p;
        }
    }

    __syncthreads();

    // Reduce s partials over 16 o-groups
    if (tid < 2 * TN) {
        int which = tid >= TN;
        int nn = which ? tid - TN : tid;
        float s = 0.f;
#pragma unroll
        for (int og = 0; og < 16; og++) s += s_red[which][og][nn];
        int n = n0 + nn;
        if (n < NN) {
            if (which) g_s2[b * NN + n] = s;
            else       g_s1[b * NN + n] = s;
        }
    }
}

// ---------------------------------------------------------------------------
// Kernel 2: attention + aggregation. One warp per node (16 nodes / block).
//   e_k = lrelu(s1[i_k] + s2[j_k]); A = softmax_k(e)
//   h[c] = sum_k A_k * wh_h[b][j_k][c]   (coalesced 256B fp16 gathers)
// Output transposed to [b][c][n] via smem staging.
// ---------------------------------------------------------------------------
__global__ void __launch_bounds__(512) gat_kernel(const int* __restrict__ ei,
                                                  float* __restrict__ out) {
    __shared__ float hs[16 * 132];  // [node_local][c], padded stride

    int tid = threadIdx.x;  // 512
    int lane = tid & 31;
    int w = tid >> 5;       // node within block, 0..15
    int b = blockIdx.y;
    int n0 = blockIdx.x * 16;
    int n = n0 + w;

    int kk = lane & 15;
    int j = ei[(((size_t)0 * BB + b) * NN + n) * KK + kk];  // edge_index[0] -> j
    int i = ei[(((size_t)1 * BB + b) * NN + n) * KK + kk];  // edge_index[1] -> i

    float e = g_s1[b * NN + i] + g_s2[b * NN + j];
    e = (e > 0.f) ? e : 0.2f * e;  // leaky relu

    float em = e;
#pragma unroll
    for (int m = 8; m; m >>= 1) em = fmaxf(em, __shfl_xor_sync(0xffffffffu, em, m));
    float p = __expf(e - em);
    float ps = p;
#pragma unroll
    for (int m = 8; m; m >>= 1) ps += __shfl_xor_sync(0xffffffffu, ps, m);
    float A = p / ps;

    // fp16 gather: row = 256 B = 32 uint2; lane owns channels [lane*4, lane*4+4)
    const uint2* whb = (const uint2*)g_whh + (size_t)b * NN * 32;
    float4 acc = make_float4(0.f, 0.f, 0.f, 0.f);
#pragma unroll
    for (int k = 0; k < 16; k++) {
        float Ak = __shfl_sync(0xffffffffu, A, k);
        int jk   = __shfl_sync(0xffffffffu, j, k);
        uint2 v = whb[(size_t)jk * 32 + lane];
        __half2 h0 = *reinterpret_cast<__half2*>(&v.x);
        __half2 h1 = *reinterpret_cast<__half2*>(&v.y);
        float2 f0 = __half22float2(h0);
        float2 f1 = __half22float2(h1);
        acc.x += Ak * f0.x;
        acc.y += Ak * f0.y;
        acc.z += Ak * f1.x;
        acc.w += Ak * f1.y;
    }

    *(float4*)&hs[w * 132 + lane * 4] = acc;
    __syncthreads();

#pragma unroll
    for (int r = 0; r < 4; r++) {
        int c = (tid >> 4) + r * 32;
        int nl = tid & 15;
        out[((size_t)b * CC + c) * NN + n0 + nl] = hs[nl * 132 + c];
    }
}

// ---------------------------------------------------------------------------
extern "C" void kernel_launch(void* const* d_in, const int* in_sizes, int n_in,
                              void* d_out, int out_size) {
    const float* x = (const float*)d_in[0];       // [B,C,N,1]
    const int* ei  = (const int*)d_in[1];         // [2,B,N,K]
    const float* W = (const float*)d_in[2];       // [C,C]
    const float* a = (const float*)d_in[3];       // [2C]
    float* out     = (float*)d_out;               // [B,C,N,1]

    gemm_kernel<<<dim3(148, BB), NTHR>>>(x, W, a);
    gat_kernel<<<dim3(NN / 16, BB), 512>>>(ei, out);
}

// round 6
// speedup vs baseline: 2.3176x; 1.3196x over previous
#include <cuda_runtime.h>
#include <cuda_fp16.h>
#include <mma.h>
#include <cstdint>

using namespace nvcuda;

#define BB 2
#define CC 128
#define NN 10000
#define KK 16
#define TM 128
#define NT ((NN + TM - 1) / TM)   // 79 tiles per batch

#define LDX 136   // halfs: ld for xh / ws staging (272 B rows)
#define LDD 140   // floats: ld for D staging (560 B rows, 4-way max conflicts)
#define DYN_SMEM 71680  // max(2*128*136*2, 128*140*4)

// Scratch (static device arrays are allowed)
__device__ __align__(16) __half g_whh[BB * NN * CC];  // node-major [b][n][c] fp16
__device__ float g_s1[BB * NN];
__device__ float g_s2[BB * NN];

extern __shared__ char dyn_smem[];

// ---------------------------------------------------------------------------
// Kernel 1: WMMA (HMMA) GEMM, fp16 in / fp32 accum.
// Per CTA: D[128 nodes x 128 o] = x^T-tile @ W^T, K = 128.
//   A: xh[c][n] fp16  == matrix_a col_major (elem(n,c) at xh + c*LDX + n)
//   B: ws[o][c] fp16  == matrix_b col_major (elem(c,o) at ws + o*LDX + c)
// Phase union: inputs then D f32 share the dynamic smem buffer.
// Epilogue: s1/s2 dots + fp16 node-major wh store, straight from D tile.
// ---------------------------------------------------------------------------
__global__ void __launch_bounds__(256) gemm_wmma(const float* __restrict__ x,
                                                 const float* __restrict__ W,
                                                 const float* __restrict__ a) {
    __shared__ float a_s[2 * CC];
    __shared__ float s_part[2][2][TM];   // [o-half][which][node]

    half*  xh = (half*)dyn_smem;                      // [CC][LDX]
    half*  ws = (half*)(dyn_smem + CC * LDX * 2);     // [CC][LDX]
    float* D  = (float*)dyn_smem;                     // phase 2: [TM][LDD]

    int tid = threadIdx.x;
    int b = blockIdx.y;
    int n0 = blockIdx.x * TM;

    a_s[tid] = a[tid];   // 256 threads cover 2*CC

    // Stage x tile -> fp16 xh[c][nn]  (coalesced float2 LDG, half2 STS)
#pragma unroll 4
    for (int it = 0; it < 32; it++) {
        int idx = it * 256 + tid;
        int c = idx >> 6;
        int n2 = idx & 63;
        int n = n0 + n2 * 2;
        const float* xp = &x[((size_t)b * CC + c) * NN + n];
        float f0 = (n < NN) ? xp[0] : 0.f;
        float f1 = (n + 1 < NN) ? xp[1] : 0.f;
        *(half2*)&xh[c * LDX + n2 * 2] = __floats2half2_rn(f0, f1);
    }
    // Stage W -> fp16 ws[o][c]
#pragma unroll 4
    for (int it = 0; it < 32; it++) {
        int idx = it * 256 + tid;
        int o = idx >> 6;
        int c2 = idx & 63;
        float2 wv = *(const float2*)&W[o * CC + c2 * 2];
        *(half2*)&ws[o * LDX + c2 * 2] = __floats2half2_rn(wv.x, wv.y);
    }
    __syncthreads();

    int w = tid >> 5;
    int ni = w >> 1;   // 0..3 -> nodes [ni*32, +32)
    int oi = w & 1;    // 0..1 -> o [oi*64, +64)

    wmma::fragment<wmma::accumulator, 16, 16, 16, float> acc[2][4];
#pragma unroll
    for (int i = 0; i < 2; i++)
#pragma unroll
        for (int j = 0; j < 4; j++) wmma::fill_fragment(acc[i][j], 0.f);

#pragma unroll
    for (int k = 0; k < 8; k++) {
        wmma::fragment<wmma::matrix_a, 16, 16, 16, half, wmma::col_major> af[2];
        wmma::fragment<wmma::matrix_b, 16, 16, 16, half, wmma::col_major> bf[4];
#pragma unroll
        for (int i = 0; i < 2; i++)
            wmma::load_matrix_sync(af[i], xh + (k * 16) * LDX + ni * 32 + i * 16, LDX);
#pragma unroll
        for (int j = 0; j < 4; j++)
            wmma::load_matrix_sync(bf[j], ws + (oi * 64 + j * 16) * LDX + k * 16, LDX);
#pragma unroll
        for (int i = 0; i < 2; i++)
#pragma unroll
            for (int j = 0; j < 4; j++)
                wmma::mma_sync(acc[i][j], af[i], bf[j], acc[i][j]);
    }
    __syncthreads();   // all input reads complete before D overwrites the buffer

#pragma unroll
    for (int i = 0; i < 2; i++)
#pragma unroll
        for (int j = 0; j < 4; j++)
            wmma::store_matrix_sync(D + (ni * 32 + i * 16) * LDD + oi * 64 + j * 16,
                                    acc[i][j], LDD, wmma::mem_row_major);
    __syncthreads();

    // Epilogue: thread -> (node = tid&127, o-half = tid>>7)
    {
        int nd = tid & 127;
        int hf = tid >> 7;
        int n = n0 + nd;
        const float* row = D + nd * LDD + hf * 64;
        float s1 = 0.f, s2 = 0.f;
        half2 hrow[32];
#pragma unroll
        for (int q = 0; q < 16; q++) {
            float4 v = *(const float4*)&row[q * 4];
            int o = hf * 64 + q * 4;
            s1 += a_s[o] * v.x + a_s[o + 1] * v.y + a_s[o + 2] * v.z + a_s[o + 3] * v.w;
            s2 += a_s[CC + o] * v.x + a_s[CC + o + 1] * v.y
                + a_s[CC + o + 2] * v.z + a_s[CC + o + 3] * v.w;
            hrow[q * 2]     = __floats2half2_rn(v.x, v.y);
            hrow[q * 2 + 1] = __floats2half2_rn(v.z, v.w);
        }
        s_part[hf][0][nd] = s1;
        s_part[hf][1][nd] = s2;
        if (n < NN) {
            uint4* dst = (uint4*)&g_whh[((size_t)b * NN + n) * CC + hf * 64];
#pragma unroll
            for (int q = 0; q < 8; q++) dst[q] = ((uint4*)hrow)[q];
        }
    }
    __syncthreads();

    // Combine s partials
    {
        int which = tid >> 7;
        int nd = tid & 127;
        int n = n0 + nd;
        if (n < NN) {
            float s = s_part[0][which][nd] + s_part[1][which][nd];
            if (which) g_s2[b * NN + n] = s;
            else       g_s1[b * NN + n] = s;
        }
    }
}

// ---------------------------------------------------------------------------
// Kernel 2: attention + aggregation (unchanged best version). Warp per node.
// ---------------------------------------------------------------------------
__global__ void __launch_bounds__(512) gat_kernel(const int* __restrict__ ei,
                                                  float* __restrict__ out) {
    __shared__ float hs[16 * 132];

    int tid = threadIdx.x;  // 512
    int lane = tid & 31;
    int w = tid >> 5;
    int b = blockIdx.y;
    int n0 = blockIdx.x * 16;
    int n = n0 + w;

    int kk = lane & 15;
    int j = ei[(((size_t)0 * BB + b) * NN + n) * KK + kk];
    int i = ei[(((size_t)1 * BB + b) * NN + n) * KK + kk];

    float e = g_s1[b * NN + i] + g_s2[b * NN + j];
    e = (e > 0.f) ? e : 0.2f * e;

    float em = e;
#pragma unroll
    for (int m = 8; m; m >>= 1) em = fmaxf(em, __shfl_xor_sync(0xffffffffu, em, m));
    float p = __expf(e - em);
    float ps = p;
#pragma unroll
    for (int m = 8; m; m >>= 1) ps += __shfl_xor_sync(0xffffffffu, ps, m);
    float A = p / ps;

    const uint2* whb = (const uint2*)g_whh + (size_t)b * NN * 32;
    float4 acc = make_float4(0.f, 0.f, 0.f, 0.f);
#pragma unroll
    for (int k = 0; k < 16; k++) {
        float Ak = __shfl_sync(0xffffffffu, A, k);
        int jk   = __shfl_sync(0xffffffffu, j, k);
        uint2 v = whb[(size_t)jk * 32 + lane];
        __half2 h0 = *reinterpret_cast<__half2*>(&v.x);
        __half2 h1 = *reinterpret_cast<__half2*>(&v.y);
        float2 f0 = __half22float2(h0);
        float2 f1 = __half22float2(h1);
        acc.x += Ak * f0.x;
        acc.y += Ak * f0.y;
        acc.z += Ak * f1.x;
        acc.w += Ak * f1.y;
    }

    *(float4*)&hs[w * 132 + lane * 4] = acc;
    __syncthreads();

#pragma unroll
    for (int r = 0; r < 4; r++) {
        int c = (tid >> 4) + r * 32;
        int nl = tid & 15;
        out[((size_t)b * CC + c) * NN + n0 + nl] = hs[nl * 132 + c];
    }
}

// ---------------------------------------------------------------------------
extern "C" void kernel_launch(void* const* d_in, const int* in_sizes, int n_in,
                              void* d_out, int out_size) {
    const float* x = (const float*)d_in[0];       // [B,C,N,1]
    const int* ei  = (const int*)d_in[1];         // [2,B,N,K]
    const float* W = (const float*)d_in[2];       // [C,C]
    const float* a = (const float*)d_in[3];       // [2C]
    float* out     = (float*)d_out;               // [B,C,N,1]

    cudaFuncSetAttribute(gemm_wmma, cudaFuncAttributeMaxDynamicSharedMemorySize,
                         DYN_SMEM);
    gemm_wmma<<<dim3(NT, BB), 256, DYN_SMEM>>>(x, W, a);
    gat_kernel<<<dim3(NN / 16, BB), 512>>>(ei, out);
}

// round 7
// speedup vs baseline: 2.6343x; 1.1367x over previous
#include <cuda_runtime.h>
#include <cuda_fp16.h>
#include <mma.h>
#include <cstdint>

using namespace nvcuda;

#define BB 2
#define CC 128
#define NN 10000
#define KK 16
#define TM 128
#define NT ((NN + TM - 1) / TM)   // 79 tiles per batch

#define LDX 136   // halfs: ld for xh / ws staging (272 B rows)
#define LDD 140   // floats: ld for D staging (560 B rows)
#define DYN_SMEM 71680  // max(2*128*136*2, 128*140*4)

// Scratch (static device arrays are allowed)
__device__ __align__(16) __half g_whh[BB * NN * CC];  // node-major [b][n][c] fp16
__device__ float g_s1[BB * NN];
__device__ float g_s2[BB * NN];

extern __shared__ char dyn_smem[];

// ---------------------------------------------------------------------------
// Kernel 1: WMMA (HMMA) GEMM, fp16 in / fp32 accum.
// Per CTA: D[128 nodes x 128 o] = x^T-tile @ W^T, K = 128.
// Staging loops FULLY unrolled -> 16+16 LDG.64 in flight (one DRAM wave).
// Phase union: inputs then D f32 share the dynamic smem buffer.
// ---------------------------------------------------------------------------
__global__ void __launch_bounds__(256) gemm_wmma(const float* __restrict__ x,
                                                 const float* __restrict__ W,
                                                 const float* __restrict__ a) {
    __shared__ float a_s[2 * CC];
    __shared__ float s_part[2][2][TM];   // [o-half][which][node]

    half*  xh = (half*)dyn_smem;                      // [CC][LDX]
    half*  ws = (half*)(dyn_smem + CC * LDX * 2);     // [CC][LDX]
    float* D  = (float*)dyn_smem;                     // phase 2: [TM][LDD]

    int tid = threadIdx.x;
    int b = blockIdx.y;
    int n0 = blockIdx.x * TM;

    a_s[tid] = a[tid];   // 256 threads cover 2*CC

    // Stage x tile -> fp16 xh[c][nn]: batch all 16 LDG.64, then convert+STS
    {
        float2 xv[16];
#pragma unroll
        for (int it = 0; it < 16; it++) {
            int idx = it * 256 + tid;        // covers 4096 float2? No: 16*256=4096 ✓
            int c = idx >> 5;                // 4096/128 c-rows of 32 float2
            int n2 = idx & 31;
            int n = n0 + n2 * 4;             // 2 float2 per... (see below)
            (void)n;
            xv[it] = make_float2(0.f, 0.f);
        }
        // NOTE: x tile is 128c x 128n = 8192 float2; do it in 32 explicit loads
        // split into two fully-unrolled batches of 16 to bound registers.
#pragma unroll
        for (int half_ = 0; half_ < 2; half_++) {
            float2 v[16];
#pragma unroll
            for (int it = 0; it < 16; it++) {
                int idx = (half_ * 16 + it) * 256 + tid;
                int c = idx >> 6;
                int n2 = idx & 63;
                int n = n0 + n2 * 2;
                const float* xp = &x[((size_t)b * CC + c) * NN + n];
                float f0 = (n < NN) ? xp[0] : 0.f;
                float f1 = (n + 1 < NN) ? xp[1] : 0.f;
                v[it] = make_float2(f0, f1);
            }
#pragma unroll
            for (int it = 0; it < 16; it++) {
                int idx = (half_ * 16 + it) * 256 + tid;
                int c = idx >> 6;
                int n2 = idx & 63;
                *(half2*)&xh[c * LDX + n2 * 2] = __floats2half2_rn(v[it].x, v[it].y);
            }
        }
    }
    // Stage W -> fp16 ws[o][c]: two batches of 16 LDG.64
    {
#pragma unroll
        for (int half_ = 0; half_ < 2; half_++) {
            float2 v[16];
#pragma unroll
            for (int it = 0; it < 16; it++) {
                int idx = (half_ * 16 + it) * 256 + tid;
                int o = idx >> 6;
                int c2 = idx & 63;
                v[it] = *(const float2*)&W[o * CC + c2 * 2];
            }
#pragma unroll
            for (int it = 0; it < 16; it++) {
                int idx = (half_ * 16 + it) * 256 + tid;
                int o = idx >> 6;
                int c2 = idx & 63;
                *(half2*)&ws[o * LDX + c2 * 2] = __floats2half2_rn(v[it].x, v[it].y);
            }
        }
    }
    __syncthreads();

    int w = tid >> 5;
    int ni = w >> 1;   // 0..3 -> nodes [ni*32, +32)
    int oi = w & 1;    // 0..1 -> o [oi*64, +64)

    wmma::fragment<wmma::accumulator, 16, 16, 16, float> acc[2][4];
#pragma unroll
    for (int i = 0; i < 2; i++)
#pragma unroll
        for (int j = 0; j < 4; j++) wmma::fill_fragment(acc[i][j], 0.f);

#pragma unroll
    for (int k = 0; k < 8; k++) {
        wmma::fragment<wmma::matrix_a, 16, 16, 16, half, wmma::col_major> af[2];
        wmma::fragment<wmma::matrix_b, 16, 16, 16, half, wmma::col_major> bf[4];
#pragma unroll
        for (int i = 0; i < 2; i++)
            wmma::load_matrix_sync(af[i], xh + (k * 16) * LDX + ni * 32 + i * 16, LDX);
#pragma unroll
        for (int j = 0; j < 4; j++)
            wmma::load_matrix_sync(bf[j], ws + (oi * 64 + j * 16) * LDX + k * 16, LDX);
#pragma unroll
        for (int i = 0; i < 2; i++)
#pragma unroll
            for (int j = 0; j < 4; j++)
                wmma::mma_sync(acc[i][j], af[i], bf[j], acc[i][j]);
    }
    __syncthreads();   // input reads complete before D overwrites the buffer

#pragma unroll
    for (int i = 0; i < 2; i++)
#pragma unroll
        for (int j = 0; j < 4; j++)
            wmma::store_matrix_sync(D + (ni * 32 + i * 16) * LDD + oi * 64 + j * 16,
                                    acc[i][j], LDD, wmma::mem_row_major);
    __syncthreads();

    // Epilogue: thread -> (node = tid&127, o-half = tid>>7)
    {
        int nd = tid & 127;
        int hf = tid >> 7;
        int n = n0 + nd;
        const float* row = D + nd * LDD + hf * 64;
        float s1 = 0.f, s2 = 0.f;
        half2 hrow[32];
#pragma unroll
        for (int q = 0; q < 16; q++) {
            float4 v = *(const float4*)&row[q * 4];
            int o = hf * 64 + q * 4;
            s1 += a_s[o] * v.x + a_s[o + 1] * v.y + a_s[o + 2] * v.z + a_s[o + 3] * v.w;
            s2 += a_s[CC + o] * v.x + a_s[CC + o + 1] * v.y
                + a_s[CC + o + 2] * v.z + a_s[CC + o + 3] * v.w;
            hrow[q * 2]     = __floats2half2_rn(v.x, v.y);
            hrow[q * 2 + 1] = __floats2half2_rn(v.z, v.w);
        }
        s_part[hf][0][nd] = s1;
        s_part[hf][1][nd] = s2;
        if (n < NN) {
            uint4* dst = (uint4*)&g_whh[((size_t)b * NN + n) * CC + hf * 64];
#pragma unroll
            for (int q = 0; q < 8; q++) dst[q] = ((uint4*)hrow)[q];
        }
    }
    __syncthreads();

    // Combine s partials
    {
        int which = tid >> 7;
        int nd = tid & 127;
        int n = n0 + nd;
        if (n < NN) {
            float s = s_part[0][which][nd] + s_part[1][which][nd];
            if (which) g_s2[b * NN + n] = s;
            else       g_s1[b * NN + n] = s;
        }
    }
}

// ---------------------------------------------------------------------------
// Kernel 2: attention + aggregation. Warp per node. Gather loop batched in
// two waves of 8 independent LDG.64 (MLP=8) to hide L2 latency.
// ---------------------------------------------------------------------------
__global__ void __launch_bounds__(512, 2) gat_kernel(const int* __restrict__ ei,
                                                     float* __restrict__ out) {
    __shared__ float hs[16 * 132];

    int tid = threadIdx.x;  // 512
    int lane = tid & 31;
    int w = tid >> 5;
    int b = blockIdx.y;
    int n0 = blockIdx.x * 16;
    int n = n0 + w;

    int kk = lane & 15;
    int j = ei[(((size_t)0 * BB + b) * NN + n) * KK + kk];
    int i = ei[(((size_t)1 * BB + b) * NN + n) * KK + kk];

    float e = g_s1[b * NN + i] + g_s2[b * NN + j];
    e = (e > 0.f) ? e : 0.2f * e;

    float em = e;
#pragma unroll
    for (int m = 8; m; m >>= 1) em = fmaxf(em, __shfl_xor_sync(0xffffffffu, em, m));
    float p = __expf(e - em);
    float ps = p;
#pragma unroll
    for (int m = 8; m; m >>= 1) ps += __shfl_xor_sync(0xffffffffu, ps, m);
    float A = p / ps;

    const uint2* whb = (const uint2*)g_whh + (size_t)b * NN * 32;
    float4 acc = make_float4(0.f, 0.f, 0.f, 0.f);

#pragma unroll
    for (int half_ = 0; half_ < 2; half_++) {
        // distribute 8 neighbor indices, issue 8 independent gathers
        int jv[8];
#pragma unroll
        for (int k = 0; k < 8; k++)
            jv[k] = __shfl_sync(0xffffffffu, j, half_ * 8 + k);
        uint2 v[8];
#pragma unroll
        for (int k = 0; k < 8; k++)
            v[k] = whb[(size_t)jv[k] * 32 + lane];
        // accumulate
#pragma unroll
        for (int k = 0; k < 8; k++) {
            float Ak = __shfl_sync(0xffffffffu, A, half_ * 8 + k);
            __half2 h0 = *reinterpret_cast<__half2*>(&v[k].x);
            __half2 h1 = *reinterpret_cast<__half2*>(&v[k].y);
            float2 f0 = __half22float2(h0);
            float2 f1 = __half22float2(h1);
            acc.x += Ak * f0.x;
            acc.y += Ak * f0.y;
            acc.z += Ak * f1.x;
            acc.w += Ak * f1.y;
        }
    }

    *(float4*)&hs[w * 132 + lane * 4] = acc;
    __syncthreads();

#pragma unroll
    for (int r = 0; r < 4; r++) {
        int c = (tid >> 4) + r * 32;
        int nl = tid & 15;
        out[((size_t)b * CC + c) * NN + n0 + nl] = hs[nl * 132 + c];
    }
}

// ---------------------------------------------------------------------------
extern "C" void kernel_launch(void* const* d_in, const int* in_sizes, int n_in,
                              void* d_out, int out_size) {
    const float* x = (const float*)d_in[0];       // [B,C,N,1]
    const int* ei  = (const int*)d_in[1];         // [2,B,N,K]
    const float* W = (const float*)d_in[2];       // [C,C]
    const float* a = (const float*)d_in[3];       // [2C]
    float* out     = (float*)d_out;               // [B,C,N,1]

    cudaFuncSetAttribute(gemm_wmma, cudaFuncAttributeMaxDynamicSharedMemorySize,
                         DYN_SMEM);
    gemm_wmma<<<dim3(NT, BB), 256, DYN_SMEM>>>(x, W, a);
    gat_kernel<<<dim3(NN / 16, BB), 512>>>(ei, out);
}

// round 8
// speedup vs baseline: 3.1363x; 1.1905x over previous
#include <cuda_runtime.h>
#include <cuda_fp16.h>
#include <mma.h>
#include <cstdint>

using namespace nvcuda;

#define BB 2
#define CC 128
#define NN 10000
#define KK 16

// ---- gemm config: one full wave (140 CTAs on 148 SMs) ----
#define TMG 144
#define NTG ((NN + TMG - 1) / TMG)   // 70
#define GT 288                       // 9 warps
#define LDN 152   // xh leading dim (halfs),  152*2B: 16B-mult ✓
#define LDW 136   // ws leading dim (halfs)
#define LDD 140   // D leading dim (floats), %4==0 ✓
#define XH_BYTES (CC * LDN * 2)          // 38912
#define WS_BYTES (CC * LDW * 2)          // 34816
#define DYN_SMEM (TMG * LDD * 4)         // 80640 > XH+WS=73728

// Scratch (static device arrays are allowed)
__device__ __align__(16) __half g_whh[BB * NN * CC];  // node-major [b][n][c] fp16
__device__ float g_s1[BB * NN];
__device__ float g_s2[BB * NN];

extern __shared__ char dyn_smem[];

// ---------------------------------------------------------------------------
// Kernel 1: WMMA GEMM, fp16 in / fp32 accum. Tile 144n x 128o, K=128.
// Grid (70, 2) = 140 CTAs -> exactly one wave. 9 warps, warp = 16n x 128o.
// ---------------------------------------------------------------------------
__global__ void __launch_bounds__(GT) gemm_wmma(const float* __restrict__ x,
                                                const float* __restrict__ W,
                                                const float* __restrict__ a) {
    __shared__ float a_s[2 * CC];
    __shared__ float s_part[2][2][TMG];

    half*  xh = (half*)dyn_smem;                 // [CC][LDN]
    half*  ws = (half*)(dyn_smem + XH_BYTES);    // [CC][LDW]
    float* D  = (float*)dyn_smem;                // phase 2: [TMG][LDD]

    int tid = threadIdx.x;
    int b = blockIdx.y;
    int n0 = blockIdx.x * TMG;

    if (tid < 2 * CC) a_s[tid] = a[tid];

    // Stage x tile -> xh[c][n] fp16 (9216 float2 loads, 32/thread, full unroll)
#pragma unroll
    for (int it = 0; it < 32; it++) {
        int idx = it * GT + tid;
        int c = idx / 72;
        int n2 = idx - c * 72;
        int n = n0 + n2 * 2;
        const float* xp = &x[((size_t)b * CC + c) * NN + n];
        float f0 = (n < NN) ? xp[0] : 0.f;
        float f1 = (n + 1 < NN) ? xp[1] : 0.f;
        *(half2*)&xh[c * LDN + n2 * 2] = __floats2half2_rn(f0, f1);
    }
    // Stage W -> ws[o][c] fp16 (8192 float2, 29 guarded iters)
#pragma unroll
    for (int it = 0; it < 29; it++) {
        int idx = it * GT + tid;
        if (idx < 8192) {
            int o = idx >> 6;
            int c2 = idx & 63;
            float2 wv = *(const float2*)&W[o * CC + c2 * 2];
            *(half2*)&ws[o * LDW + c2 * 2] = __floats2half2_rn(wv.x, wv.y);
        }
    }
    __syncthreads();

    int w = tid >> 5;   // 0..8, rows [w*16, +16)

    wmma::fragment<wmma::accumulator, 16, 16, 16, float> acc[8];
#pragma unroll
    for (int j = 0; j < 8; j++) wmma::fill_fragment(acc[j], 0.f);

#pragma unroll
    for (int k = 0; k < 8; k++) {
        wmma::fragment<wmma::matrix_a, 16, 16, 16, half, wmma::col_major> af;
        wmma::load_matrix_sync(af, xh + (k * 16) * LDN + w * 16, LDN);
#pragma unroll
        for (int j = 0; j < 8; j++) {
            wmma::fragment<wmma::matrix_b, 16, 16, 16, half, wmma::col_major> bf;
            wmma::load_matrix_sync(bf, ws + (j * 16) * LDW + k * 16, LDW);
            wmma::mma_sync(acc[j], af, bf, acc[j]);
        }
    }
    __syncthreads();   // all input reads done before D overwrites buffer

#pragma unroll
    for (int j = 0; j < 8; j++)
        wmma::store_matrix_sync(D + (w * 16) * LDD + j * 16, acc[j], LDD,
                                wmma::mem_row_major);
    __syncthreads();

    // Epilogue: thread -> (node nd, o-half hf)
    {
        int hf = tid / TMG;          // 0/1
        int nd = tid - hf * TMG;
        int n = n0 + nd;
        const float* row = D + nd * LDD + hf * 64;
        float s1 = 0.f, s2 = 0.f;
        half2 hrow[32];
#pragma unroll
        for (int q = 0; q < 16; q++) {
            float4 v = *(const float4*)&row[q * 4];
            int o = hf * 64 + q * 4;
            s1 += a_s[o] * v.x + a_s[o + 1] * v.y + a_s[o + 2] * v.z + a_s[o + 3] * v.w;
            s2 += a_s[CC + o] * v.x + a_s[CC + o + 1] * v.y
                + a_s[CC + o + 2] * v.z + a_s[CC + o + 3] * v.w;
            hrow[q * 2]     = __floats2half2_rn(v.x, v.y);
            hrow[q * 2 + 1] = __floats2half2_rn(v.z, v.w);
        }
        s_part[hf][0][nd] = s1;
        s_part[hf][1][nd] = s2;
        if (n < NN) {
            uint4* dst = (uint4*)&g_whh[((size_t)b * NN + n) * CC + hf * 64];
#pragma unroll
            for (int q = 0; q < 8; q++) dst[q] = ((uint4*)hrow)[q];
        }
    }
    __syncthreads();

    // Combine s partials
    {
        int which = tid / TMG;
        int nd = tid - which * TMG;
        int n = n0 + nd;
        if (n < NN) {
            float s = s_part[0][which][nd] + s_part[1][which][nd];
            if (which) g_s2[b * NN + n] = s;
            else       g_s1[b * NN + n] = s;
        }
    }
}

// ---------------------------------------------------------------------------
// Kernel 2: attention + aggregation. TWO nodes per warp (lanes 0-15 node A,
// 16-31 node B): one LDG.128 per k serves both nodes; softmax confined to
// 16-lane halves. Batch-4 gather pipelining. 256 thr = 16 nodes/block.
// ---------------------------------------------------------------------------
__global__ void __launch_bounds__(256) gat_kernel(const int* __restrict__ ei,
                                                  float* __restrict__ out) {
    __shared__ float hs[16 * 132];   // [node_local][c], padded

    int tid = threadIdx.x;   // 256
    int lane = tid & 31;
    int w = tid >> 5;        // 0..7
    int b = blockIdx.y;
    int n0 = blockIdx.x * 16;          // grid.x = 625, 10000 = 16*625 exact
    int nh = lane >> 4;                // node half 0/1
    int nl = 2 * w + nh;               // node local 0..15
    int n = n0 + nl;
    int kk = lane & 15;

    int j = ei[(((size_t)0 * BB + b) * NN + n) * KK + kk];
    int i = ei[(((size_t)1 * BB + b) * NN + n) * KK + kk];

    float e = g_s1[b * NN + i] + g_s2[b * NN + j];
    e = (e > 0.f) ? e : 0.2f * e;

    // softmax within each 16-lane half
    float em = e;
#pragma unroll
    for (int m = 8; m; m >>= 1) em = fmaxf(em, __shfl_xor_sync(0xffffffffu, em, m));
    float p = __expf(e - em);
    float ps = p;
#pragma unroll
    for (int m = 8; m; m >>= 1) ps += __shfl_xor_sync(0xffffffffu, ps, m);
    float A = p / ps;

    // gather: lane owns channels [kk*8, kk*8+8) of its node (uint4 = 16B fp16)
    const uint4* whb = (const uint4*)g_whh + (size_t)b * NN * 16;
    int hbase = lane & 16;   // shfl source base for this half
    float acc[8];
#pragma unroll
    for (int q = 0; q < 8; q++) acc[q] = 0.f;

#pragma unroll
    for (int batch = 0; batch < 4; batch++) {
        uint4 v[4];
#pragma unroll
        for (int t = 0; t < 4; t++) {
            int jk = __shfl_sync(0xffffffffu, j, hbase + batch * 4 + t);
            v[t] = whb[(size_t)jk * 16 + kk];
        }
#pragma unroll
        for (int t = 0; t < 4; t++) {
            float Ak = __shfl_sync(0xffffffffu, A, hbase + batch * 4 + t);
            const __half2* h = (const __half2*)&v[t];
#pragma unroll
            for (int q = 0; q < 4; q++) {
                float2 f = __half22float2(h[q]);
                acc[2 * q]     += Ak * f.x;
                acc[2 * q + 1] += Ak * f.y;
            }
        }
    }

    *(float4*)&hs[nl * 132 + kk * 8]     = *(float4*)&acc[0];
    *(float4*)&hs[nl * 132 + kk * 8 + 4] = *(float4*)&acc[4];
    __syncthreads();

    // transposed coalesced write: out[b][c][n0..n0+16)
#pragma unroll
    for (int r = 0; r < 8; r++) {
        int c = (tid >> 4) + r * 16;
        int nn = tid & 15;
        out[((size_t)b * CC + c) * NN + n0 + nn] = hs[nn * 132 + c];
    }
}

// ---------------------------------------------------------------------------
extern "C" void kernel_launch(void* const* d_in, const int* in_sizes, int n_in,
                              void* d_out, int out_size) {
    const float* x = (const float*)d_in[0];       // [B,C,N,1]
    const int* ei  = (const int*)d_in[1];         // [2,B,N,K]
    const float* W = (const float*)d_in[2];       // [C,C]
    const float* a = (const float*)d_in[3];       // [2C]
    float* out     = (float*)d_out;               // [B,C,N,1]

    cudaFuncSetAttribute(gemm_wmma, cudaFuncAttributeMaxDynamicSharedMemorySize,
                         DYN_SMEM);
    gemm_wmma<<<dim3(NTG, BB), GT, DYN_SMEM>>>(x, W, a);
    gat_kernel<<<dim3(NN / 16, BB), 256>>>(ei, out);
}